// round 6
// baseline (speedup 1.0000x reference)
#include <cuda_runtime.h>
#include <cuda_bf16.h>
#include <math.h>

#define PN 20
#define MAXB 32768

// scratch: per-point bundle {rx,ry,rz,cd,dens,0,0,0} = 32B; per-batch 640B
__device__ float g_scr[MAXB * PN * 8];
__device__ int   g_nvc[MAXB];

__device__ __forceinline__ void stg_cs_v8(float* p, const float* o) {
    asm volatile("st.global.cs.v8.b32 [%0], {%1,%2,%3,%4,%5,%6,%7,%8};"
        :: "l"(p),
           "r"(__float_as_uint(o[0])), "r"(__float_as_uint(o[1])),
           "r"(__float_as_uint(o[2])), "r"(__float_as_uint(o[3])),
           "r"(__float_as_uint(o[4])), "r"(__float_as_uint(o[5])),
           "r"(__float_as_uint(o[6])), "r"(__float_as_uint(o[7]))
        : "memory");
}

// ===================== kernel A: compute scalars ============================
__global__ __launch_bounds__(256)
void spf_compute(const float* __restrict__ points,
                 const float* __restrict__ mask,
                 int B)
{
    const int lane = threadIdx.x & 31;
    const long long b = (long long)blockIdx.x * 8 + (threadIdx.x >> 5);
    if (b >= B) return;

    float px = 0.f, py = 0.f, pz = 0.f, m = 0.f;
    if (lane < PN) {
        const float* pp = points + b * (PN * 3) + lane * 3;
        px = pp[0]; py = pp[1]; pz = pp[2];
        m  = mask[b * PN + lane];
    }
    // valid count + centroid
    float nvf = m, cx = m * px, cy = m * py, cz = m * pz;
    #pragma unroll
    for (int o = 16; o > 0; o >>= 1) {
        nvf += __shfl_xor_sync(0xffffffffu, nvf, o);
        cx  += __shfl_xor_sync(0xffffffffu, cx,  o);
        cy  += __shfl_xor_sync(0xffffffffu, cy,  o);
        cz  += __shfl_xor_sync(0xffffffffu, cz,  o);
    }
    int nvi = (int)(nvf + 0.5f);
    int nvc = nvi < 1 ? 1 : nvi;
    float inv = 1.f / (float)nvc;
    cx *= inv; cy *= inv; cz *= inv;

    float rx = px - cx, ry = py - cy, rz = pz - cz;
    float cd = sqrtf(rx * rx + ry * ry + rz * rz);

    // top-3 NN on squared distances (sqrt deferred to 3)
    float e0 = 3e38f, e1 = 3e38f, e2 = 3e38f;
    #pragma unroll
    for (int j = 0; j < PN; j++) {
        float qx = __shfl_sync(0xffffffffu, px, j);
        float qy = __shfl_sync(0xffffffffu, py, j);
        float qz = __shfl_sync(0xffffffffu, pz, j);
        float mj = __shfl_sync(0xffffffffu, m,  j);
        float dx = px - qx, dy = py - qy, dz = pz - qz;
        float d2 = fmaxf(dx * dx + dy * dy + dz * dz, 1e-12f);
        if (j == lane || mj <= 0.f) d2 = 3e38f;
        if (d2 < e0)      { e2 = e1; e1 = e0; e0 = d2; }
        else if (d2 < e1) { e2 = e1; e1 = d2; }
        else if (d2 < e2) { e2 = d2; }
    }
    float dens = 0.f;
    if (m > 0.f && nvi > 1) {
        int k = nvi - 1; if (k > 3) k = 3;
        float s = sqrtf(e0);
        if (k > 1) s += sqrtf(e1);
        if (k > 2) s += sqrtf(e2);
        dens = s / (float)k;
    }

    if (lane < PN) {
        float4* d = (float4*)(g_scr + (b * PN + lane) * 8);
        d[0] = make_float4(rx, ry, rz, cd);
        d[1] = make_float4(dens, 0.f, 0.f, 0.f);
    }
    if (lane == 0) g_nvc[b] = nvc;
}

// ===================== kernel B: pure store stream ==========================
__global__ __launch_bounds__(256)
void spf_store(const float* __restrict__ W_rel,     // [3,64]
               const float* __restrict__ b_rel,     // [64]
               const float* __restrict__ W_dist,    // [1,64]
               const float* __restrict__ b_dist,    // [64]
               const float* __restrict__ emb_count, // [50,64]
               const float* __restrict__ W_den,     // [1,64]
               const float* __restrict__ b_den,     // [64]
               float* __restrict__ out,             // [B,20,256]
               int B)
{
    __shared__ float sv[8][PN * 8];   // per-warp scalar bundles

    const int lane = threadIdx.x & 31;
    const int w    = threadIdx.x >> 5;
    const long long b = (long long)blockIdx.x * 8 + w;
    if (b >= B) return;

    // lane owns 8-channel chunk `lane` of each 256-ch row
    const int g  = lane >> 3;          // 0=rel 1=dist 2=count 3=den
    const int lc = (lane & 7) * 8;

    // scalar selection indices into bundle {rx,ry,rz,cd,dens,0,0,0}
    const int i1 = (g == 0) ? 0 : ((g == 1) ? 3 : ((g == 3) ? 4 : 5));
    const int i2 = (g == 0) ? 1 : 5;
    const int i3 = (g == 0) ? 2 : 5;

    // stage this batch's 640B scalar block (coalesced, L2-resident)
    const float* src = g_scr + b * (PN * 8);
    #pragma unroll
    for (int i = 0; i < 5; i++)
        sv[w][lane + 32 * i] = src[lane + 32 * i];

    // per-lane weights: o = s1*P + s2*Q + s3*R + F
    const int nvc = g_nvc[b];          // same addr across warp -> 1 sector
    float P[8], Q[8], R[8], F[8];
    #pragma unroll
    for (int q = 0; q < 8; q++) {
        int c = lc + q;
        float p_, f_;
        if (g == 0)      { p_ = W_rel[c];  f_ = b_rel[c];  }
        else if (g == 1) { p_ = W_dist[c]; f_ = b_dist[c]; }
        else if (g == 3) { p_ = W_den[c];  f_ = b_den[c];  }
        else             { p_ = 0.f;       f_ = emb_count[(size_t)nvc * 64 + c]; }
        P[q] = p_;
        Q[q] = (g == 0) ? W_rel[64 + c]  : 0.f;
        R[q] = (g == 0) ? W_rel[128 + c] : 0.f;
        F[q] = f_;
    }
    __syncwarp();

    // store burst: 20 rows x 1KB; one 32B v8 store per lane per row
    float* ob = out + (size_t)b * (PN * 256);
    #pragma unroll 5
    for (int n = 0; n < PN; n++) {
        const float* s = &sv[w][n * 8];
        float s1 = s[i1], s2 = s[i2], s3 = s[i3];
        float o[8];
        #pragma unroll
        for (int q = 0; q < 8; q++)
            o[q] = fmaf(s1, P[q], fmaf(s2, Q[q], fmaf(s3, R[q], F[q])));
        stg_cs_v8(ob + n * 256 + lane * 8, o);
    }
}

extern "C" void kernel_launch(void* const* d_in, const int* in_sizes, int n_in,
                              void* d_out, int out_size) {
    const float* points    = (const float*)d_in[0];
    const float* mask      = (const float*)d_in[1];
    const float* W_rel     = (const float*)d_in[2];
    const float* b_rel     = (const float*)d_in[3];
    const float* W_dist    = (const float*)d_in[4];
    const float* b_dist    = (const float*)d_in[5];
    const float* emb_count = (const float*)d_in[6];
    const float* W_den     = (const float*)d_in[7];
    const float* b_den     = (const float*)d_in[8];
    float* out = (float*)d_out;

    int B = in_sizes[0] / (PN * 3);
    if (B > MAXB) B = MAXB;
    int grid = (B + 7) / 8;

    spf_compute<<<grid, 256>>>(points, mask, B);
    spf_store<<<grid, 256>>>(W_rel, b_rel, W_dist, b_dist,
                             emb_count, W_den, b_den, out, B);
}

// round 7
// speedup vs baseline: 1.1691x; 1.1691x over previous
#include <cuda_runtime.h>
#include <cuda_bf16.h>
#include <math.h>

#define PN 20
#define ST 8           // batches per stage (one per warp)
#define NS 2           // stages per CTA  -> 16 batches per CTA

__device__ __forceinline__ void stg_cs_v8(float* p, const float* o) {
    asm volatile("st.global.cs.v8.b32 [%0], {%1,%2,%3,%4,%5,%6,%7,%8};"
        :: "l"(p),
           "r"(__float_as_uint(o[0])), "r"(__float_as_uint(o[1])),
           "r"(__float_as_uint(o[2])), "r"(__float_as_uint(o[3])),
           "r"(__float_as_uint(o[4])), "r"(__float_as_uint(o[5])),
           "r"(__float_as_uint(o[6])), "r"(__float_as_uint(o[7]))
        : "memory");
}

__global__ __launch_bounds__(256)
void spf_kernel(const float* __restrict__ points,
                const float* __restrict__ mask,
                const float* __restrict__ W_rel,     // [3,64]
                const float* __restrict__ b_rel,     // [64]
                const float* __restrict__ W_dist,    // [1,64]
                const float* __restrict__ b_dist,    // [64]
                const float* __restrict__ emb_count, // [50,64]
                const float* __restrict__ W_den,     // [1,64]
                const float* __restrict__ b_den,     // [64]
                float* __restrict__ out,             // [B,20,256]
                int B)
{
    // double-buffered per-point scalar bundles {rx,ry,rz,cd,dens,0,0,0}
    __shared__ float sv[NS][ST][PN][8];
    __shared__ float semb[NS][ST][64];

    const int t    = threadIdx.x;
    const int lane = t & 31;
    const int w    = t >> 5;
    const long long b0 = (long long)blockIdx.x * (ST * NS);

    // ---------------- store-role constants (fixed per thread) ----------------
    const int j8 = t & 31;           // 8-channel chunk within 256-ch row
    const int g  = j8 >> 3;          // 0=rel 1=dist 2=count 3=den
    const int lc = (j8 & 7) * 8;
    const int n0 = t >> 5;           // base row; rows n0, n0+8, n0+16(<20)
    const int i1 = (g == 0) ? 0 : ((g == 1) ? 3 : ((g == 3) ? 4 : 5));
    const int i2 = (g == 0) ? 1 : 5;
    const int i3 = (g == 0) ? 2 : 5;

    float P[8], Q[8], R[8], F[8];
    #pragma unroll
    for (int q = 0; q < 8; q++) {
        int c = lc + q;
        float p_, f_;
        if (g == 0)      { p_ = W_rel[c];  f_ = b_rel[c];  }
        else if (g == 1) { p_ = W_dist[c]; f_ = b_dist[c]; }
        else if (g == 3) { p_ = W_den[c];  f_ = b_den[c];  }
        else             { p_ = 0.f;       f_ = 0.f;       } // g==2: per batch
        P[q] = p_;
        Q[q] = (g == 0) ? W_rel[64 + c]  : 0.f;
        R[q] = (g == 0) ? W_rel[128 + c] : 0.f;
        F[q] = f_;
    }

    // ---------------- per-warp compute (batch bb -> buffers[s]) --------------
    auto compute = [&](long long bb, int s, float px, float py, float pz, float m) {
        float nvf = m, cx = m * px, cy = m * py, cz = m * pz;
        #pragma unroll
        for (int o = 16; o > 0; o >>= 1) {
            nvf += __shfl_xor_sync(0xffffffffu, nvf, o);
            cx  += __shfl_xor_sync(0xffffffffu, cx,  o);
            cy  += __shfl_xor_sync(0xffffffffu, cy,  o);
            cz  += __shfl_xor_sync(0xffffffffu, cz,  o);
        }
        int nvi = (int)(nvf + 0.5f);
        int nvc = nvi < 1 ? 1 : nvi;
        float inv = 1.f / (float)nvc;
        cx *= inv; cy *= inv; cz *= inv;

        float rx = px - cx, ry = py - cy, rz = pz - cz;
        float cd = sqrtf(rx * rx + ry * ry + rz * rz);

        float e0 = 3e38f, e1 = 3e38f, e2 = 3e38f;
        #pragma unroll
        for (int j = 0; j < PN; j++) {
            float qx = __shfl_sync(0xffffffffu, px, j);
            float qy = __shfl_sync(0xffffffffu, py, j);
            float qz = __shfl_sync(0xffffffffu, pz, j);
            float mj = __shfl_sync(0xffffffffu, m,  j);
            float dx = px - qx, dy = py - qy, dz = pz - qz;
            float d2 = fmaxf(dx * dx + dy * dy + dz * dz, 1e-12f);
            if (j == lane || mj <= 0.f) d2 = 3e38f;
            if (d2 < e0)      { e2 = e1; e1 = e0; e0 = d2; }
            else if (d2 < e1) { e2 = e1; e1 = d2; }
            else if (d2 < e2) { e2 = d2; }
        }
        float dens = 0.f;
        if (m > 0.f && nvi > 1) {
            int k = nvi - 1; if (k > 3) k = 3;
            float s2_ = sqrtf(e0);
            if (k > 1) s2_ += sqrtf(e1);
            if (k > 2) s2_ += sqrtf(e2);
            dens = s2_ / (float)k;
        }
        if (lane < PN) {
            float* d = sv[s][w][lane];
            d[0] = rx; d[1] = ry; d[2] = rz; d[3] = cd;
            d[4] = dens; d[5] = 0.f; d[6] = 0.f; d[7] = 0.f;
        }
        semb[s][w][lane]      = emb_count[(size_t)nvc * 64 + lane];
        semb[s][w][lane + 32] = emb_count[(size_t)nvc * 64 + lane + 32];
    };

    // ---------------- store burst for one stage -------------------------------
    auto store_stage = [&](int s, long long bs) {
        float Floc[8];
        #pragma unroll
        for (int q = 0; q < 8; q++) Floc[q] = F[q];
        #pragma unroll
        for (int w2 = 0; w2 < ST; w2++) {
            long long bb = bs + w2;
            if (bb >= B) break;
            if (g == 2) {
                #pragma unroll
                for (int q = 0; q < 8; q++) Floc[q] = semb[s][w2][lc + q];
            }
            float* obw = out + (size_t)bb * (PN * 256);
            #pragma unroll
            for (int r = 0; r < 3; r++) {
                int n = n0 + 8 * r;
                if (n >= PN) break;
                const float* sc = sv[s][w2][n];
                float s1 = sc[i1], s2 = sc[i2], s3 = sc[i3];
                float o[8];
                #pragma unroll
                for (int q = 0; q < 8; q++)
                    o[q] = fmaf(s1, P[q], fmaf(s2, Q[q], fmaf(s3, R[q], Floc[q])));
                stg_cs_v8(obw + n * 256 + j8 * 8, o);
            }
        }
    };

    // ================================ pipeline ================================
    const long long bA = b0 + w;          // stage-0 batch for this warp
    const long long bB = b0 + ST + w;     // stage-1 batch for this warp

    // load stage-0 points
    float px0 = 0.f, py0 = 0.f, pz0 = 0.f, m0 = 0.f;
    if (bA < B && lane < PN) {
        const float* pp = points + bA * (PN * 3) + lane * 3;
        px0 = pp[0]; py0 = pp[1]; pz0 = pp[2];
        m0  = mask[bA * PN + lane];
    }
    if (bA < B) compute(bA, 0, px0, py0, pz0, m0);

    // prefetch stage-1 points before the barrier (drains under store-0)
    float px1 = 0.f, py1 = 0.f, pz1 = 0.f, m1 = 0.f;
    if (bB < B && lane < PN) {
        const float* pp = points + bB * (PN * 3) + lane * 3;
        px1 = pp[0]; py1 = pp[1]; pz1 = pp[2];
        m1  = mask[bB * PN + lane];
    }
    __syncthreads();

    // store stage 0 (fire-and-forget), then compute stage 1 while STGs drain
    store_stage(0, b0);
    if (bB < B) compute(bB, 1, px1, py1, pz1, m1);
    __syncthreads();

    store_stage(1, b0 + ST);
}

extern "C" void kernel_launch(void* const* d_in, const int* in_sizes, int n_in,
                              void* d_out, int out_size) {
    const float* points    = (const float*)d_in[0];
    const float* mask      = (const float*)d_in[1];
    const float* W_rel     = (const float*)d_in[2];
    const float* b_rel     = (const float*)d_in[3];
    const float* W_dist    = (const float*)d_in[4];
    const float* b_dist    = (const float*)d_in[5];
    const float* emb_count = (const float*)d_in[6];
    const float* W_den     = (const float*)d_in[7];
    const float* b_den     = (const float*)d_in[8];
    float* out = (float*)d_out;

    int B = in_sizes[0] / (PN * 3);
    int perCta = ST * NS;
    int grid = (B + perCta - 1) / perCta;
    spf_kernel<<<grid, 256>>>(points, mask, W_rel, b_rel, W_dist, b_dist,
                              emb_count, W_den, b_den, out, B);
}

// round 8
// speedup vs baseline: 1.2192x; 1.0428x over previous
#include <cuda_runtime.h>
#include <cuda_bf16.h>
#include <math.h>

#define PN 20
#define GB 8          // batches per CTA (one per warp)

__device__ __forceinline__ void stg_cs_v8(float* p, const float* o) {
    asm volatile("st.global.cs.v8.b32 [%0], {%1,%2,%3,%4,%5,%6,%7,%8};"
        :: "l"(p),
           "r"(__float_as_uint(o[0])), "r"(__float_as_uint(o[1])),
           "r"(__float_as_uint(o[2])), "r"(__float_as_uint(o[3])),
           "r"(__float_as_uint(o[4])), "r"(__float_as_uint(o[5])),
           "r"(__float_as_uint(o[6])), "r"(__float_as_uint(o[7]))
        : "memory");
}

__global__ __launch_bounds__(256, 4)
void spf_kernel(const float* __restrict__ points,
                const float* __restrict__ mask,
                const float* __restrict__ W_rel,     // [3,64]
                const float* __restrict__ b_rel,     // [64]
                const float* __restrict__ W_dist,    // [1,64]
                const float* __restrict__ b_dist,    // [64]
                const float* __restrict__ emb_count, // [50,64]
                const float* __restrict__ W_den,     // [1,64]
                const float* __restrict__ b_den,     // [64]
                float* __restrict__ out,             // [B,20,256]
                int B)
{
    // per-point scalar bundle: {rx,ry,rz,cd,dens,0,0,0}
    __shared__ float sv[GB][PN][8];
    __shared__ float semb[GB][64];

    const int t    = threadIdx.x;
    const int lane = t & 31;
    const int w    = t >> 5;
    const long long b0 = (long long)blockIdx.x * GB;

    // ================= compute phase: warp w owns batch b0+w =================
    if (b0 + w < B) {
        const long long b = b0 + w;
        float px = 0.f, py = 0.f, pz = 0.f, m = 0.f;
        if (lane < PN) {
            const float* pp = points + b * (PN * 3) + lane * 3;
            px = pp[0]; py = pp[1]; pz = pp[2];
            m  = mask[b * PN + lane];
        }
        // valid count + centroid
        float nvf = m, cx = m * px, cy = m * py, cz = m * pz;
        #pragma unroll
        for (int o = 16; o > 0; o >>= 1) {
            nvf += __shfl_xor_sync(0xffffffffu, nvf, o);
            cx  += __shfl_xor_sync(0xffffffffu, cx,  o);
            cy  += __shfl_xor_sync(0xffffffffu, cy,  o);
            cz  += __shfl_xor_sync(0xffffffffu, cz,  o);
        }
        int nvi = (int)(nvf + 0.5f);
        int nvc = nvi < 1 ? 1 : nvi;
        float inv = 1.f / (float)nvc;
        cx *= inv; cy *= inv; cz *= inv;

        float rx = px - cx, ry = py - cy, rz = pz - cz;
        float cd = sqrtf(rx * rx + ry * ry + rz * rz);

        // top-3 nearest neighbors on SQUARED distances (sqrt deferred to 3)
        float e0 = 3e38f, e1 = 3e38f, e2 = 3e38f;
        #pragma unroll
        for (int j = 0; j < PN; j++) {
            float qx = __shfl_sync(0xffffffffu, px, j);
            float qy = __shfl_sync(0xffffffffu, py, j);
            float qz = __shfl_sync(0xffffffffu, pz, j);
            float mj = __shfl_sync(0xffffffffu, m,  j);
            float dx = px - qx, dy = py - qy, dz = pz - qz;
            float d2 = fmaxf(dx * dx + dy * dy + dz * dz, 1e-12f);
            if (j == lane || mj <= 0.f) d2 = 3e38f;
            if (d2 < e0)      { e2 = e1; e1 = e0; e0 = d2; }
            else if (d2 < e1) { e2 = e1; e1 = d2; }
            else if (d2 < e2) { e2 = d2; }
        }
        float dens = 0.f;
        if (m > 0.f && nvi > 1) {
            int k = nvi - 1; if (k > 3) k = 3;
            float s = sqrtf(e0);
            if (k > 1) s += sqrtf(e1);
            if (k > 2) s += sqrtf(e2);
            dens = s / (float)k;
        }

        if (lane < PN) {
            float* d = sv[w][lane];
            d[0] = rx; d[1] = ry; d[2] = rz; d[3] = cd;
            d[4] = dens; d[5] = 0.f; d[6] = 0.f; d[7] = 0.f;
        }
        semb[w][lane]      = __ldg(emb_count + (size_t)nvc * 64 + lane);
        semb[w][lane + 32] = __ldg(emb_count + (size_t)nvc * 64 + lane + 32);
    }
    __syncthreads();

    // ================= store phase: branch-free unified epilogue =============
    // thread owns fixed 8-channel chunk j8 (32B); rows n0, n0+8, (n0+16 if n0<4)
    const int j8 = t & 31;
    const int g  = j8 >> 3;          // 0=rel, 1=dist, 2=count, 3=den
    const int lc = (j8 & 7) * 8;     // channel base within group
    const int n0 = t >> 5;           // 0..7

    // scalar selection indices into sv[.][n][8] (slot 5 is always 0)
    const int i1 = (g == 0) ? 0 : ((g == 1) ? 3 : ((g == 3) ? 4 : 5));
    const int i2 = (g == 0) ? 1 : 5;
    const int i3 = (g == 0) ? 2 : 5;

    // per-lane weights: o = s1*P + s2*Q + s3*R + F
    float P[8], Q[8], R[8], F[8];
    #pragma unroll
    for (int q = 0; q < 8; q++) {
        int c = lc + q;
        float p_, f_;
        if (g == 0)      { p_ = __ldg(W_rel + c);  f_ = __ldg(b_rel + c);  }
        else if (g == 1) { p_ = __ldg(W_dist + c); f_ = __ldg(b_dist + c); }
        else if (g == 3) { p_ = __ldg(W_den + c);  f_ = __ldg(b_den + c);  }
        else             { p_ = 0.f;               f_ = 0.f;               }
        P[q] = p_;
        Q[q] = (g == 0) ? __ldg(W_rel + 64 + c)  : 0.f;
        R[q] = (g == 0) ? __ldg(W_rel + 128 + c) : 0.f;
        F[q] = f_;
    }

    const bool row3 = (n0 < PN - 16);   // n0 < 4
    float* outB = out + (size_t)b0 * (PN * 256);
    #pragma unroll
    for (int w2 = 0; w2 < GB; w2++) {
        if (b0 + w2 >= B) break;
        if (g == 2) {
            #pragma unroll
            for (int q = 0; q < 8; q++) F[q] = semb[w2][lc + q];
        }
        float* obw = outB + (size_t)w2 * (PN * 256);
        #pragma unroll
        for (int r = 0; r < 3; r++) {
            if (r == 2 && !row3) break;
            int n = n0 + 8 * r;
            const float* s = sv[w2][n];
            float s1 = s[i1], s2 = s[i2], s3 = s[i3];
            float o[8];
            #pragma unroll
            for (int q = 0; q < 8; q++)
                o[q] = fmaf(s1, P[q], fmaf(s2, Q[q], fmaf(s3, R[q], F[q])));
            stg_cs_v8(obw + n * 256 + j8 * 8, o);
        }
    }
}

extern "C" void kernel_launch(void* const* d_in, const int* in_sizes, int n_in,
                              void* d_out, int out_size) {
    const float* points    = (const float*)d_in[0];
    const float* mask      = (const float*)d_in[1];
    const float* W_rel     = (const float*)d_in[2];
    const float* b_rel     = (const float*)d_in[3];
    const float* W_dist    = (const float*)d_in[4];
    const float* b_dist    = (const float*)d_in[5];
    const float* emb_count = (const float*)d_in[6];
    const float* W_den     = (const float*)d_in[7];
    const float* b_den     = (const float*)d_in[8];
    float* out = (float*)d_out;

    int B = in_sizes[0] / (PN * 3);
    int grid = (B + GB - 1) / GB;
    spf_kernel<<<grid, 256>>>(points, mask, W_rel, b_rel, W_dist, b_dist,
                              emb_count, W_den, b_den, out, B);
}

// round 9
// speedup vs baseline: 1.2292x; 1.0082x over previous
#include <cuda_runtime.h>
#include <cuda_bf16.h>
#include <math.h>

#define PN 20
#define GB 8          // batches per CTA (one per warp)

__device__ __forceinline__ void stg_v8(float* p, const float* o) {
    asm volatile("st.global.v8.b32 [%0], {%1,%2,%3,%4,%5,%6,%7,%8};"
        :: "l"(p),
           "r"(__float_as_uint(o[0])), "r"(__float_as_uint(o[1])),
           "r"(__float_as_uint(o[2])), "r"(__float_as_uint(o[3])),
           "r"(__float_as_uint(o[4])), "r"(__float_as_uint(o[5])),
           "r"(__float_as_uint(o[6])), "r"(__float_as_uint(o[7]))
        : "memory");
}

__global__ __launch_bounds__(256, 4)
void spf_kernel(const float* __restrict__ points,
                const float* __restrict__ mask,
                const float* __restrict__ W_rel,     // [3,64]
                const float* __restrict__ b_rel,     // [64]
                const float* __restrict__ W_dist,    // [1,64]
                const float* __restrict__ b_dist,    // [64]
                const float* __restrict__ emb_count, // [50,64]
                const float* __restrict__ W_den,     // [1,64]
                const float* __restrict__ b_den,     // [64]
                float* __restrict__ out,             // [B,20,256]
                int B)
{
    // per-point scalar bundle: {rx,ry,rz,cd,dens,0,0,0}
    __shared__ float sv[GB][PN][8];
    __shared__ float semb[GB][64];

    const int t    = threadIdx.x;
    const int lane = t & 31;
    const int w    = t >> 5;
    const long long b0 = (long long)blockIdx.x * GB;

    // ================= compute phase: warp w owns batch b0+w =================
    if (b0 + w < B) {
        const long long b = b0 + w;
        float px = 0.f, py = 0.f, pz = 0.f, m = 0.f;
        if (lane < PN) {
            const float* pp = points + b * (PN * 3) + lane * 3;
            px = pp[0]; py = pp[1]; pz = pp[2];
            m  = mask[b * PN + lane];
        }
        // valid count + centroid
        float nvf = m, cx = m * px, cy = m * py, cz = m * pz;
        #pragma unroll
        for (int o = 16; o > 0; o >>= 1) {
            nvf += __shfl_xor_sync(0xffffffffu, nvf, o);
            cx  += __shfl_xor_sync(0xffffffffu, cx,  o);
            cy  += __shfl_xor_sync(0xffffffffu, cy,  o);
            cz  += __shfl_xor_sync(0xffffffffu, cz,  o);
        }
        int nvi = (int)(nvf + 0.5f);
        int nvc = nvi < 1 ? 1 : nvi;
        float inv = 1.f / (float)nvc;
        cx *= inv; cy *= inv; cz *= inv;

        float rx = px - cx, ry = py - cy, rz = pz - cz;
        float cd = sqrtf(rx * rx + ry * ry + rz * rz);

        // top-3 nearest neighbors on SQUARED distances (sqrt deferred to 3)
        float e0 = 3e38f, e1 = 3e38f, e2 = 3e38f;
        #pragma unroll
        for (int j = 0; j < PN; j++) {
            float qx = __shfl_sync(0xffffffffu, px, j);
            float qy = __shfl_sync(0xffffffffu, py, j);
            float qz = __shfl_sync(0xffffffffu, pz, j);
            float mj = __shfl_sync(0xffffffffu, m,  j);
            float dx = px - qx, dy = py - qy, dz = pz - qz;
            float d2 = fmaxf(dx * dx + dy * dy + dz * dz, 1e-12f);
            if (j == lane || mj <= 0.f) d2 = 3e38f;
            if (d2 < e0)      { e2 = e1; e1 = e0; e0 = d2; }
            else if (d2 < e1) { e2 = e1; e1 = d2; }
            else if (d2 < e2) { e2 = d2; }
        }
        float dens = 0.f;
        if (m > 0.f && nvi > 1) {
            int k = nvi - 1; if (k > 3) k = 3;
            float s = sqrtf(e0);
            if (k > 1) s += sqrtf(e1);
            if (k > 2) s += sqrtf(e2);
            dens = s / (float)k;
        }

        if (lane < PN) {
            float* d = sv[w][lane];
            d[0] = rx; d[1] = ry; d[2] = rz; d[3] = cd;
            d[4] = dens; d[5] = 0.f; d[6] = 0.f; d[7] = 0.f;
        }
        semb[w][lane]      = __ldg(emb_count + (size_t)nvc * 64 + lane);
        semb[w][lane + 32] = __ldg(emb_count + (size_t)nvc * 64 + lane + 32);
    }
    __syncthreads();

    // ================= store phase: branch-free unified epilogue =============
    // thread owns fixed 8-channel chunk j8 (32B); rows n0, n0+8, (n0+16 if n0<4)
    const int j8 = t & 31;
    const int g  = j8 >> 3;          // 0=rel, 1=dist, 2=count, 3=den
    const int lc = (j8 & 7) * 8;     // channel base within group
    const int n0 = t >> 5;           // 0..7

    // scalar selection indices into sv[.][n][8] (slot 5 is always 0)
    const int i1 = (g == 0) ? 0 : ((g == 1) ? 3 : ((g == 3) ? 4 : 5));
    const int i2 = (g == 0) ? 1 : 5;
    const int i3 = (g == 0) ? 2 : 5;

    // per-lane weights: o = s1*P + s2*Q + s3*R + F
    float P[8], Q[8], R[8], F[8];
    #pragma unroll
    for (int q = 0; q < 8; q++) {
        int c = lc + q;
        float p_, f_;
        if (g == 0)      { p_ = __ldg(W_rel + c);  f_ = __ldg(b_rel + c);  }
        else if (g == 1) { p_ = __ldg(W_dist + c); f_ = __ldg(b_dist + c); }
        else if (g == 3) { p_ = __ldg(W_den + c);  f_ = __ldg(b_den + c);  }
        else             { p_ = 0.f;               f_ = 0.f;               }
        P[q] = p_;
        Q[q] = (g == 0) ? __ldg(W_rel + 64 + c)  : 0.f;
        R[q] = (g == 0) ? __ldg(W_rel + 128 + c) : 0.f;
        F[q] = f_;
    }

    const bool row3 = (n0 < PN - 16);   // n0 < 4
    float* outB = out + (size_t)b0 * (PN * 256);
    #pragma unroll
    for (int w2 = 0; w2 < GB; w2++) {
        if (b0 + w2 >= B) break;
        if (g == 2) {
            #pragma unroll
            for (int q = 0; q < 8; q++) F[q] = semb[w2][lc + q];
        }
        float* obw = outB + (size_t)w2 * (PN * 256);
        #pragma unroll
        for (int r = 0; r < 3; r++) {
            if (r == 2 && !row3) break;
            int n = n0 + 8 * r;
            const float* s = sv[w2][n];
            float s1 = s[i1], s2 = s[i2], s3 = s[i3];
            float o[8];
            #pragma unroll
            for (int q = 0; q < 8; q++)
                o[q] = fmaf(s1, P[q], fmaf(s2, Q[q], fmaf(s3, R[q], F[q])));
            stg_v8(obw + n * 256 + j8 * 8, o);
        }
    }
}

extern "C" void kernel_launch(void* const* d_in, const int* in_sizes, int n_in,
                              void* d_out, int out_size) {
    const float* points    = (const float*)d_in[0];
    const float* mask      = (const float*)d_in[1];
    const float* W_rel     = (const float*)d_in[2];
    const float* b_rel     = (const float*)d_in[3];
    const float* W_dist    = (const float*)d_in[4];
    const float* b_dist    = (const float*)d_in[5];
    const float* emb_count = (const float*)d_in[6];
    const float* W_den     = (const float*)d_in[7];
    const float* b_den     = (const float*)d_in[8];
    float* out = (float*)d_out;

    int B = in_sizes[0] / (PN * 3);
    int grid = (B + GB - 1) / GB;
    spf_kernel<<<grid, 256>>>(points, mask, W_rel, b_rel, W_dist, b_dist,
                              emb_count, W_den, b_den, out, B);
}